// round 2
// baseline (speedup 1.0000x reference)
#include <cuda_runtime.h>
#include <math.h>

#define BGRAPH 128
#define NPG    512
#define NNODES (BGRAPH*NPG)        // 65536
#define EPG    (NPG*16)            // 8192 edges per graph
#define NEDGE  (NNODES*16)         // 1048576 per side

// ---- scratch (__device__ globals; no allocation) ----
__device__ int   g_cnt[2][NNODES];
__device__ int   g_cur[2][NNODES];
__device__ int   g_off[2][NNODES];
__device__ float g_inv[2][NNODES];
__device__ int   g_csr[2][NEDGE];          // graph-LOCAL src ids
__device__ float g_h[2][(size_t)NNODES*64];
__device__ float g_u[2][3][BGRAPH*10*64];

// ---------------- build kernels ----------------
__global__ void k_zero() {
    int i = blockIdx.x*blockDim.x + threadIdx.x;
    if (i < 2*NNODES) { ((int*)g_cnt)[i] = 0; ((int*)g_cur)[i] = 0; }
}

__global__ void k_count(const int* __restrict__ ei, const int* __restrict__ ej) {
    int i = blockIdx.x*blockDim.x + threadIdx.x;
    if (i < NEDGE) {
        atomicAdd(&g_cnt[0][ei[NEDGE+i]], 1);
        atomicAdd(&g_cnt[1][ej[NEDGE+i]], 1);
    }
}

__global__ void k_scan() {
    int side = blockIdx.y, g = blockIdx.x, t = threadIdx.x;
    __shared__ int s[NPG];
    int n = g*NPG + t;
    int c = g_cnt[side][n];
    g_inv[side][n] = rsqrtf((float)c + 1.0f);
    s[t] = c; __syncthreads();
    for (int d = 1; d < NPG; d <<= 1) {
        int v = (t >= d) ? s[t-d] : 0;
        __syncthreads();
        s[t] += v;
        __syncthreads();
    }
    g_off[side][n] = g*EPG + s[t] - c;   // exclusive, absolute
}

__global__ void k_fill(const int* __restrict__ ei, const int* __restrict__ ej) {
    int i = blockIdx.x*blockDim.x + threadIdx.x;
    if (i < NEDGE) {
        int s0 = ei[i], d0 = ei[NEDGE+i];
        int p0 = atomicAdd(&g_cur[0][d0], 1);
        g_csr[0][g_off[0][d0] + p0] = s0 & (NPG-1);   // store LOCAL id
        int s1 = ej[i], d1 = ej[NEDGE+i];
        int p1 = atomicAdd(&g_cur[1][d1], 1);
        g_csr[1][g_off[1][d1] + p1] = s1 & (NPG-1);   // store LOCAL id
    }
}

// ---------------- fused GCN layer: XW + aggregate + bias/relu + resize taps ----------------
template<int FI, int FO, bool RELU>
__global__ void __launch_bounds__(512, 1)
k_gcn(const float* __restrict__ x0, const float* __restrict__ x1,
      const float* __restrict__ W, const float* __restrict__ bias, int li) {
    extern __shared__ float sm[];
    float* Wsh   = sm;                         // FI*FO
    float* invsh = Wsh + FI*FO;                // 512
    int*   offsh = (int*)(invsh + NPG);        // 513
    int*   csrsh = offsh + NPG + 1;            // 8192
    float* xwsh  = (float*)(csrsh + EPG);      // 512*FO

    int side = blockIdx.y, g = blockIdx.x, tid = threadIdx.x;
    const float* in = (li == 0) ? (side ? x1 : x0) : &g_h[side][0];

    for (int i = tid; i < FI*FO; i += 512) Wsh[i] = W[i];
    invsh[tid] = g_inv[side][g*NPG + tid];
    offsh[tid] = g_off[side][g*NPG + tid] - g*EPG;   // LOCAL offsets
    if (tid == 0) offsh[NPG] = EPG;
    for (int i = tid; i < EPG; i += 512) csrsh[i] = g_csr[side][g*EPG + i];
    __syncthreads();

    int warp = tid >> 5, lane = tid & 31;
    int c0 = lane & (FO-1);

    // XW into SMEM: warp per row, lane per output col
    for (int n = warp; n < NPG; n += 16) {
        const float* row = in + (size_t)(g*NPG + n)*64;
        float a0 = 0.f, a1 = 0.f;
        #pragma unroll 8
        for (int k = 0; k < FI; k++) {
            float xv = __ldg(row + k);
            a0 = fmaf(xv, Wsh[k*FO + c0], a0);
            if (FO == 64) a1 = fmaf(xv, Wsh[k*FO + lane + 32], a1);
        }
        xwsh[n*FO + c0] = a0;
        if (FO == 64)  xwsh[n*FO + lane + 32] = a1;
    }
    __syncthreads();

    // Aggregate: out[n] = inv[n]*(sum_e xw[src]*inv[src] + xw[n]*inv[n]) + b
    for (int n = warp; n < NPG; n += 16) {
        int e0 = offsh[n];
        int e1 = offsh[n+1];
        float a0 = 0.f, a1 = 0.f;
        for (int e = e0; e < e1; e++) {
            int s = csrsh[e];                  // local id
            float w = invsh[s];
            a0 = fmaf(xwsh[s*FO + c0], w, a0);
            if (FO == 64) a1 = fmaf(xwsh[s*FO + lane + 32], w, a1);
        }
        float iv = invsh[n];
        float o0 = (a0 + xwsh[n*FO + c0]*iv)*iv + __ldg(bias + c0);
        if (RELU) o0 = fmaxf(o0, 0.f);
        if (lane < FO) g_h[side][(size_t)(g*NPG + n)*64 + c0] = o0;
        if (FO == 64) {
            float o1 = (a1 + xwsh[n*FO + lane + 32]*iv)*iv + __ldg(bias + lane + 32);
            if (RELU) o1 = fmaxf(o1, 0.f);
            g_h[side][(size_t)(g*NPG + n)*64 + lane + 32] = o1;
        }
    }
    __syncthreads();

    // Bilinear-resize row projection: u[p,d] = (1-w1)*h[i0,d] + w1*h[i0+1,d]
    const float SCALE = 0.01953125f;   // 10/512, exact in fp32
    for (int t = tid; t < 10*FO; t += 512) {
        int p = t / FO, d = t % FO;
        float c = (p + 0.5f)/SCALE - 0.5f;
        int i0 = (int)floorf(c);
        float w1 = c - (float)i0;
        float v0 = g_h[side][(size_t)(g*NPG + i0    )*64 + d];
        float v1 = g_h[side][(size_t)(g*NPG + i0 + 1)*64 + d];
        g_u[side][li][g*640 + p*64 + d] = v0*(1.f - w1) + v1*w1;
    }
}

// ---------------- head: 10x10 sims + conv3x3 + MLP + sigmoid ----------------
__global__ void __launch_bounds__(128)
k_head(const float* __restrict__ cw0, const float* __restrict__ cb0,
       const float* __restrict__ cw1, const float* __restrict__ cb1,
       const float* __restrict__ cw2, const float* __restrict__ cb2,
       const float* __restrict__ mw0, const float* __restrict__ mb0,
       const float* __restrict__ mw1, const float* __restrict__ mb1,
       const float* __restrict__ mw2, const float* __restrict__ mb2,
       const float* __restrict__ mw3, const float* __restrict__ mb3,
       const float* __restrict__ mw4, const float* __restrict__ mb4,
       const float* __restrict__ sw,  const float* __restrict__ sb,
       float* __restrict__ out) {
    int b = blockIdx.x, tid = threadIdx.x;
    __shared__ float ui[3][640], uj[3][640];
    __shared__ float sim[100];
    __shared__ float feat[2400];
    __shared__ float red[4][32];
    __shared__ float a0[32], a1[16], a2[8], a3[4];

    for (int l = 0; l < 3; l++)
        for (int t = tid; t < 640; t += 128) {
            ui[l][t] = g_u[0][l][b*640 + t];
            uj[l][t] = g_u[1][l][b*640 + t];
        }
    __syncthreads();

    const int FOs[3] = {64, 32, 16};
    for (int l = 0; l < 3; l++) {
        int fo = FOs[l];
        if (tid < 100) {
            int p = tid/10, q = tid%10;
            float s = 0.f;
            for (int d = 0; d < fo; d++) s = fmaf(ui[l][p*64+d], uj[l][q*64+d], s);
            sim[tid] = s;
        }
        __syncthreads();
        const float* cw = (l==0) ? cw0 : (l==1) ? cw1 : cw2;
        const float* cb = (l==0) ? cb0 : (l==1) ? cb1 : cb2;
        for (int t = tid; t < 800; t += 128) {
            int ch = t/100, rc = t%100, r = rc/10, c = rc%10;
            float acc = __ldg(cb + ch);
            #pragma unroll
            for (int dr = 0; dr < 3; dr++)
                #pragma unroll
                for (int dc = 0; dc < 3; dc++) {
                    int rr = r + dr - 1, cc = c + dc - 1;
                    if (rr >= 0 && rr < 10 && cc >= 0 && cc < 10)
                        acc = fmaf(__ldg(cw + ch*9 + dr*3 + dc), sim[rr*10+cc], acc);
                }
            feat[l*800 + t] = fmaxf(acc, 0.f);
        }
        __syncthreads();
    }

    // MLP0: 2400 -> 32 (4-way split-K)
    {
        int o = tid & 31, part = tid >> 5;
        float acc = 0.f;
        for (int k = part; k < 2400; k += 4)
            acc = fmaf(feat[k], __ldg(mw0 + k*32 + o), acc);
        red[part][o] = acc;
    }
    __syncthreads();
    if (tid < 32)
        a0[tid] = fmaxf(red[0][tid]+red[1][tid]+red[2][tid]+red[3][tid] + __ldg(mb0+tid), 0.f);
    __syncthreads();
    if (tid < 16) { float s = __ldg(mb1+tid); for (int k=0;k<32;k++) s = fmaf(a0[k], __ldg(mw1+k*16+tid), s); a1[tid] = fmaxf(s,0.f); }
    __syncthreads();
    if (tid < 8)  { float s = __ldg(mb2+tid); for (int k=0;k<16;k++) s = fmaf(a1[k], __ldg(mw2+k*8+tid),  s); a2[tid] = fmaxf(s,0.f); }
    __syncthreads();
    if (tid < 4)  { float s = __ldg(mb3+tid); for (int k=0;k<8;k++)  s = fmaf(a2[k], __ldg(mw3+k*4+tid),  s); a3[tid] = fmaxf(s,0.f); }
    __syncthreads();
    if (tid == 0) {
        float s = __ldg(mb4);
        for (int k = 0; k < 4; k++) s = fmaf(a3[k], __ldg(mw4+k), s);
        float f = fmaxf(s, 0.f);
        float sc = f*__ldg(sw) + __ldg(sb);
        out[b] = 1.f / (1.f + expf(-sc));
    }
}

// ---------------- launch ----------------
extern "C" void kernel_launch(void* const* d_in, const int* in_sizes, int n_in,
                              void* d_out, int out_size) {
    const float* x_i = (const float*)d_in[0];
    const float* x_j = (const float*)d_in[1];
    const float* gw0 = (const float*)d_in[2];  const float* gb0 = (const float*)d_in[3];
    const float* gw1 = (const float*)d_in[4];  const float* gb1 = (const float*)d_in[5];
    const float* gw2 = (const float*)d_in[6];  const float* gb2 = (const float*)d_in[7];
    const float* cw0 = (const float*)d_in[8];  const float* cb0 = (const float*)d_in[9];
    const float* cw1 = (const float*)d_in[10]; const float* cb1 = (const float*)d_in[11];
    const float* cw2 = (const float*)d_in[12]; const float* cb2 = (const float*)d_in[13];
    const float* mw0 = (const float*)d_in[14]; const float* mb0 = (const float*)d_in[15];
    const float* mw1 = (const float*)d_in[16]; const float* mb1 = (const float*)d_in[17];
    const float* mw2 = (const float*)d_in[18]; const float* mb2 = (const float*)d_in[19];
    const float* mw3 = (const float*)d_in[20]; const float* mb3 = (const float*)d_in[21];
    const float* mw4 = (const float*)d_in[22]; const float* mb4 = (const float*)d_in[23];
    const float* sw  = (const float*)d_in[24]; const float* sb  = (const float*)d_in[25];
    const int*   ei  = (const int*)d_in[26];
    const int*   ej  = (const int*)d_in[27];

    size_t smem0 = (size_t)(64*64 + 512 + 512*64)*4 + (513 + EPG)*4;   // 184324
    size_t smem1 = (size_t)(64*32 + 512 + 512*32)*4 + (513 + EPG)*4;   // 110596
    size_t smem2 = (size_t)(32*16 + 512 + 512*16)*4 + (513 + EPG)*4;   //  71684
    cudaFuncSetAttribute(k_gcn<64,64,true >, cudaFuncAttributeMaxDynamicSharedMemorySize, (int)smem0);
    cudaFuncSetAttribute(k_gcn<64,32,true >, cudaFuncAttributeMaxDynamicSharedMemorySize, (int)smem1);
    cudaFuncSetAttribute(k_gcn<32,16,false>, cudaFuncAttributeMaxDynamicSharedMemorySize, (int)smem2);

    k_zero <<<(2*NNODES + 255)/256, 256>>>();
    k_count<<<(NEDGE + 255)/256, 256>>>(ei, ej);
    k_scan <<<dim3(BGRAPH, 2), NPG>>>();
    k_fill <<<(NEDGE + 255)/256, 256>>>(ei, ej);

    k_gcn<64,64,true ><<<dim3(BGRAPH,2), 512, smem0>>>(x_i, x_j, gw0, gb0, 0);
    k_gcn<64,32,true ><<<dim3(BGRAPH,2), 512, smem1>>>(nullptr, nullptr, gw1, gb1, 1);
    k_gcn<32,16,false><<<dim3(BGRAPH,2), 512, smem2>>>(nullptr, nullptr, gw2, gb2, 2);

    k_head<<<BGRAPH, 128>>>(cw0, cb0, cw1, cb1, cw2, cb2,
                            mw0, mb0, mw1, mb1, mw2, mb2, mw3, mb3, mw4, mb4,
                            sw, sb, (float*)d_out);
}

// round 3
// speedup vs baseline: 2.2940x; 2.2940x over previous
#include <cuda_runtime.h>
#include <math.h>

#define BGRAPH 128
#define NPG    512
#define NNODES (BGRAPH*NPG)
#define EPG    (NPG*16)            // 8192 edges per graph
#define NEDGE  (NNODES*16)

// only cross-kernel scratch: resize-tap projections
__device__ float g_u[2][3][BGRAPH*640];

// ---------------- XW stage: Y[n,c] = (sum_k X[n,k] W[k,c]) * inv[n] ----------------
template<int FI, int FO, int R>
__device__ __forceinline__ void xw_stage(
    const float* __restrict__ Xs, int xstride, int row0, int nrows,
    float* __restrict__ Ys, const float* __restrict__ W,
    const unsigned short* __restrict__ offsh, int warp, int lane)
{
    const int c0 = lane & (FO - 1);
    for (int grp = warp; grp < nrows / R; grp += 16) {
        int r0 = grp * R;
        float acc0[R], acc1[R];
        #pragma unroll
        for (int r = 0; r < R; r++) { acc0[r] = 0.f; acc1[r] = 0.f; }
        #pragma unroll 4
        for (int k = 0; k < FI; k += 4) {
            float w0[4], w1[4];
            #pragma unroll
            for (int q = 0; q < 4; q++) {
                w0[q] = __ldg(W + (k + q) * FO + c0);
                if (FO == 64) w1[q] = __ldg(W + (k + q) * FO + c0 + 32);
            }
            #pragma unroll
            for (int r = 0; r < R; r++) {
                const float4 xv = *(const float4*)(Xs + (r0 + r) * xstride + k);
                acc0[r] = fmaf(xv.x, w0[0], acc0[r]);
                acc0[r] = fmaf(xv.y, w0[1], acc0[r]);
                acc0[r] = fmaf(xv.z, w0[2], acc0[r]);
                acc0[r] = fmaf(xv.w, w0[3], acc0[r]);
                if (FO == 64) {
                    acc1[r] = fmaf(xv.x, w1[0], acc1[r]);
                    acc1[r] = fmaf(xv.y, w1[1], acc1[r]);
                    acc1[r] = fmaf(xv.z, w1[2], acc1[r]);
                    acc1[r] = fmaf(xv.w, w1[3], acc1[r]);
                }
            }
        }
        #pragma unroll
        for (int r = 0; r < R; r++) {
            int n = row0 + r0 + r;
            float inv = rsqrtf((float)(offsh[n + 1] - offsh[n]) + 1.0f);
            if (FO >= 32 || lane < FO) Ys[n * FO + c0] = acc0[r] * inv;
            if (FO == 64)              Ys[n * FO + c0 + 32] = acc1[r] * inv;
        }
    }
}

// ---------------- aggregation with direct write (layers 1,2) ----------------
template<int FO>
__device__ __forceinline__ void agg_direct(
    const float* __restrict__ Ys, float* __restrict__ Out,
    const int* __restrict__ csr, const unsigned short* __restrict__ offsh,
    const float* __restrict__ bias, bool relu, int warp, int lane)
{
    const int c0 = lane & (FO - 1);
    const float b0 = __ldg(bias + c0);
    for (int n = warp; n < NPG; n += 16) {
        int e0 = offsh[n], e1 = offsh[n + 1];
        float a0 = Ys[n * FO + c0];
        int e = e0;
        for (; e + 1 < e1; e += 2) {
            int sA = csr[e], sB = csr[e + 1];
            float vA = Ys[sA * FO + c0];
            float vB = Ys[sB * FO + c0];
            a0 += vA; a0 += vB;
        }
        if (e < e1) a0 += Ys[csr[e] * FO + c0];
        float inv = rsqrtf((float)(e1 - e0) + 1.0f);
        float o0 = a0 * inv + b0;
        if (relu) o0 = fmaxf(o0, 0.f);
        if (FO >= 32 || lane < FO) Out[n * FO + c0] = o0;
    }
}

// ---------------- resize-tap projection ----------------
template<int FO>
__device__ __forceinline__ void taps(const float* __restrict__ Hs, int stride,
                                     float* __restrict__ uout, int tid)
{
    for (int t = tid; t < 10 * FO; t += 512) {
        int p = t / FO, d = t % FO;
        float c = (p + 0.5f) * 51.2f - 0.5f;
        int i0 = (int)floorf(c);
        float w = c - (float)i0;
        uout[p * 64 + d] = Hs[i0 * stride + d] * (1.f - w) + Hs[(i0 + 1) * stride + d] * w;
    }
}

// ---------------- fused per-(graph,side) kernel ----------------
__global__ void __launch_bounds__(512, 1)
k_fused(const float* __restrict__ x0, const float* __restrict__ x1,
        const float* __restrict__ W0, const float* __restrict__ b0,
        const float* __restrict__ W1, const float* __restrict__ b1,
        const float* __restrict__ W2, const float* __restrict__ b2,
        const int* __restrict__ ei, const int* __restrict__ ej)
{
    extern __shared__ float sm[];
    float* xbuf = sm;                                   // 512*64 floats (128KB)
    float* ybuf = sm + 32768;                           // 512*32 floats (64KB)
    int*   csr  = (int*)(sm + 49152);                   // 8192 ints (32KB)
    unsigned short* offsh = (unsigned short*)(sm + 57344); // 513 ushort

    const int side = blockIdx.y, g = blockIdx.x;
    const int tid = threadIdx.x, warp = tid >> 5, lane = tid & 31;
    const int* E    = side ? ej : ei;
    const int* esrc = E + g * EPG;
    const int* edst = E + NEDGE + g * EPG;
    const float* xin = side ? x1 : x0;

    // ---- build CSR in SMEM ----
    int* cnt = (int*)ybuf;        // 512 ints
    int* cur = cnt + 512;         // 512 ints
    cnt[tid] = 0;
    __syncthreads();
    for (int e = tid; e < EPG; e += 512) atomicAdd(&cnt[edst[e] & (NPG - 1)], 1);
    __syncthreads();
    int myc = cnt[tid];
    for (int d = 1; d < NPG; d <<= 1) {
        int t = (tid >= d) ? cnt[tid - d] : 0;
        __syncthreads();
        cnt[tid] += t;
        __syncthreads();
    }
    offsh[tid + 1] = (unsigned short)cnt[tid];
    cur[tid] = cnt[tid] - myc;
    if (tid == 0) offsh[0] = 0;
    __syncthreads();
    for (int e = tid; e < EPG; e += 512) {
        int s = esrc[e] & (NPG - 1), d = edst[e] & (NPG - 1);
        int p = atomicAdd(&cur[d], 1);
        csr[p] = s;
    }
    __syncthreads();

    // ---- layer 0: XW in two 256-row chunks staged through ybuf ----
    for (int ch = 0; ch < 2; ch++) {
        const float4* src = (const float4*)(xin + ((size_t)g * NPG + ch * 256) * 64);
        float4* dst = (float4*)ybuf;
        for (int i = tid; i < 4096; i += 512) dst[i] = src[i];
        __syncthreads();
        xw_stage<64, 64, 8>(ybuf, 64, ch * 256, 256, xbuf, W0, offsh, warp, lane);
        __syncthreads();
    }

    // ---- agg0 (reads all of xbuf -> stage h0 in registers) ----
    {
        float h0[32], h1[32];
        const float bb0 = __ldg(b0 + lane);
        const float bb1 = __ldg(b0 + lane + 32);
        #pragma unroll
        for (int it = 0; it < 32; it++) {
            int n = warp + it * 16;
            int e0 = offsh[n], e1 = offsh[n + 1];
            float a0 = xbuf[n * 64 + lane];
            float a1 = xbuf[n * 64 + lane + 32];
            int e = e0;
            for (; e + 1 < e1; e += 2) {
                int sA = csr[e], sB = csr[e + 1];
                a0 += xbuf[sA * 64 + lane];
                a1 += xbuf[sA * 64 + lane + 32];
                a0 += xbuf[sB * 64 + lane];
                a1 += xbuf[sB * 64 + lane + 32];
            }
            if (e < e1) {
                int sA = csr[e];
                a0 += xbuf[sA * 64 + lane];
                a1 += xbuf[sA * 64 + lane + 32];
            }
            float inv = rsqrtf((float)(e1 - e0) + 1.0f);
            h0[it] = fmaxf(a0 * inv + bb0, 0.f);
            h1[it] = fmaxf(a1 * inv + bb1, 0.f);
        }
        __syncthreads();
        #pragma unroll
        for (int it = 0; it < 32; it++) {
            int n = warp + it * 16;
            xbuf[n * 64 + lane] = h0[it];
            xbuf[n * 64 + lane + 32] = h1[it];
        }
        __syncthreads();
    }

    // ---- taps0 + XW1 (both only read xbuf) ----
    taps<64>(xbuf, 64, &g_u[side][0][g * 640], tid);
    xw_stage<64, 32, 8>(xbuf, 64, 0, NPG, ybuf, W1, offsh, warp, lane);
    __syncthreads();

    // ---- agg1: ybuf -> xbuf (stride 32) ----
    agg_direct<32>(ybuf, xbuf, csr, offsh, b1, true, warp, lane);
    __syncthreads();

    // ---- taps1 + XW2: xbuf(stride32) -> ybuf(512x16) ----
    taps<32>(xbuf, 32, &g_u[side][1][g * 640], tid);
    xw_stage<32, 16, 8>(xbuf, 32, 0, NPG, ybuf, W2, offsh, warp, lane);
    __syncthreads();

    // ---- agg2: ybuf -> xbuf (stride 16), no relu ----
    agg_direct<16>(ybuf, xbuf, csr, offsh, b2, false, warp, lane);
    __syncthreads();

    // ---- taps2 ----
    taps<16>(xbuf, 16, &g_u[side][2][g * 640], tid);
}

// ---------------- head: 10x10 sims + conv3x3 + MLP + sigmoid ----------------
__global__ void __launch_bounds__(128)
k_head(const float* __restrict__ cw0, const float* __restrict__ cb0,
       const float* __restrict__ cw1, const float* __restrict__ cb1,
       const float* __restrict__ cw2, const float* __restrict__ cb2,
       const float* __restrict__ mw0, const float* __restrict__ mb0,
       const float* __restrict__ mw1, const float* __restrict__ mb1,
       const float* __restrict__ mw2, const float* __restrict__ mb2,
       const float* __restrict__ mw3, const float* __restrict__ mb3,
       const float* __restrict__ mw4, const float* __restrict__ mb4,
       const float* __restrict__ sw,  const float* __restrict__ sb,
       float* __restrict__ out) {
    int b = blockIdx.x, tid = threadIdx.x;
    __shared__ float ui[3][640], uj[3][640];
    __shared__ float sim[100];
    __shared__ float feat[2400];
    __shared__ float red[4][32];
    __shared__ float a0[32], a1[16], a2[8], a3[4];

    for (int l = 0; l < 3; l++)
        for (int t = tid; t < 640; t += 128) {
            ui[l][t] = g_u[0][l][b*640 + t];
            uj[l][t] = g_u[1][l][b*640 + t];
        }
    __syncthreads();

    const int FOs[3] = {64, 32, 16};
    for (int l = 0; l < 3; l++) {
        int fo = FOs[l];
        if (tid < 100) {
            int p = tid/10, q = tid%10;
            float s = 0.f;
            for (int d = 0; d < fo; d++) s = fmaf(ui[l][p*64+d], uj[l][q*64+d], s);
            sim[tid] = s;
        }
        __syncthreads();
        const float* cw = (l==0) ? cw0 : (l==1) ? cw1 : cw2;
        const float* cb = (l==0) ? cb0 : (l==1) ? cb1 : cb2;
        for (int t = tid; t < 800; t += 128) {
            int ch = t/100, rc = t%100, r = rc/10, c = rc%10;
            float acc = __ldg(cb + ch);
            #pragma unroll
            for (int dr = 0; dr < 3; dr++)
                #pragma unroll
                for (int dc = 0; dc < 3; dc++) {
                    int rr = r + dr - 1, cc = c + dc - 1;
                    if (rr >= 0 && rr < 10 && cc >= 0 && cc < 10)
                        acc = fmaf(__ldg(cw + ch*9 + dr*3 + dc), sim[rr*10+cc], acc);
                }
            feat[l*800 + t] = fmaxf(acc, 0.f);
        }
        __syncthreads();
    }

    {
        int o = tid & 31, part = tid >> 5;
        float acc = 0.f;
        for (int k = part; k < 2400; k += 4)
            acc = fmaf(feat[k], __ldg(mw0 + k*32 + o), acc);
        red[part][o] = acc;
    }
    __syncthreads();
    if (tid < 32)
        a0[tid] = fmaxf(red[0][tid]+red[1][tid]+red[2][tid]+red[3][tid] + __ldg(mb0+tid), 0.f);
    __syncthreads();
    if (tid < 16) { float s = __ldg(mb1+tid); for (int k=0;k<32;k++) s = fmaf(a0[k], __ldg(mw1+k*16+tid), s); a1[tid] = fmaxf(s,0.f); }
    __syncthreads();
    if (tid < 8)  { float s = __ldg(mb2+tid); for (int k=0;k<16;k++) s = fmaf(a1[k], __ldg(mw2+k*8+tid),  s); a2[tid] = fmaxf(s,0.f); }
    __syncthreads();
    if (tid < 4)  { float s = __ldg(mb3+tid); for (int k=0;k<8;k++)  s = fmaf(a2[k], __ldg(mw3+k*4+tid),  s); a3[tid] = fmaxf(s,0.f); }
    __syncthreads();
    if (tid == 0) {
        float s = __ldg(mb4);
        for (int k = 0; k < 4; k++) s = fmaf(a3[k], __ldg(mw4+k), s);
        float f = fmaxf(s, 0.f);
        float sc = f*__ldg(sw) + __ldg(sb);
        out[b] = 1.f / (1.f + expf(-sc));
    }
}

// ---------------- launch ----------------
extern "C" void kernel_launch(void* const* d_in, const int* in_sizes, int n_in,
                              void* d_out, int out_size) {
    const float* x_i = (const float*)d_in[0];
    const float* x_j = (const float*)d_in[1];
    const float* gw0 = (const float*)d_in[2];  const float* gb0 = (const float*)d_in[3];
    const float* gw1 = (const float*)d_in[4];  const float* gb1 = (const float*)d_in[5];
    const float* gw2 = (const float*)d_in[6];  const float* gb2 = (const float*)d_in[7];
    const float* cw0 = (const float*)d_in[8];  const float* cb0 = (const float*)d_in[9];
    const float* cw1 = (const float*)d_in[10]; const float* cb1 = (const float*)d_in[11];
    const float* cw2 = (const float*)d_in[12]; const float* cb2 = (const float*)d_in[13];
    const float* mw0 = (const float*)d_in[14]; const float* mb0 = (const float*)d_in[15];
    const float* mw1 = (const float*)d_in[16]; const float* mb1 = (const float*)d_in[17];
    const float* mw2 = (const float*)d_in[18]; const float* mb2 = (const float*)d_in[19];
    const float* mw3 = (const float*)d_in[20]; const float* mb3 = (const float*)d_in[21];
    const float* mw4 = (const float*)d_in[22]; const float* mb4 = (const float*)d_in[23];
    const float* sw  = (const float*)d_in[24]; const float* sb  = (const float*)d_in[25];
    const int*   ei  = (const int*)d_in[26];
    const int*   ej  = (const int*)d_in[27];

    const size_t smem = 57344*4 + 514*2;   // 230404 B < 232448 B cap
    static int inited = 0;
    cudaFuncSetAttribute(k_fused, cudaFuncAttributeMaxDynamicSharedMemorySize, (int)smem);
    (void)inited;

    k_fused<<<dim3(BGRAPH, 2), 512, smem>>>(x_i, x_j, gw0, gb0, gw1, gb1, gw2, gb2, ei, ej);
    k_head<<<BGRAPH, 128>>>(cw0, cb0, cw1, cb1, cw2, cb2,
                            mw0, mb0, mw1, mb1, mw2, mb2, mw3, mb3, mw4, mb4,
                            sw, sb, (float*)d_out);
}

// round 4
// speedup vs baseline: 2.4173x; 1.0538x over previous
#include <cuda_runtime.h>
#include <math.h>

#define BGRAPH 128
#define NPG    512
#define NNODES (BGRAPH*NPG)
#define EPG    (NPG*16)            // 8192 edges per graph
#define NEDGE  (NNODES*16)
#define CSR_MAX (EPG + NPG*3)      // padded-to-4 worst case = 9728

// cross-kernel scratch: resize-tap projections
__device__ float g_u[2][3][BGRAPH*640];

// SMEM byte offsets for k_fused
#define OFF_XBUF  0                       // 512*64 f  = 131072 B
#define OFF_YBUF  131072                  // 512*32 f  =  65536 B
#define OFF_CSR   196608                  // ushort[9728] = 19456 B
#define OFF_OFFS  216064                  // ushort[513]  ->  1028 B (padded)
#define OFF_INV   217092                  // float[512]   =  2048 B
#define OFF_PAD   219140                  // uchar[512]   =   512 B
#define SMEM_BYTES 219652

// ---------------- XW stage: Y[n,c] = (sum_k X[n,k] W[k,c]) * inv[n] ----------------
template<int FI, int FO, int R>
__device__ __forceinline__ void xw_stage(
    const float* __restrict__ Xs, int xstride, int row0, int nrows,
    float* __restrict__ Ys, const float* __restrict__ W,
    const float* __restrict__ invsh, int warp, int lane)
{
    const int c0 = lane & (FO - 1);
    for (int grp = warp; grp < nrows / R; grp += 16) {
        int r0 = grp * R;
        float acc0[R], acc1[R];
        #pragma unroll
        for (int r = 0; r < R; r++) { acc0[r] = 0.f; acc1[r] = 0.f; }
        #pragma unroll 4
        for (int k = 0; k < FI; k += 4) {
            float w0[4], w1[4];
            #pragma unroll
            for (int q = 0; q < 4; q++) {
                w0[q] = __ldg(W + (k + q) * FO + c0);
                if (FO == 64) w1[q] = __ldg(W + (k + q) * FO + c0 + 32);
            }
            #pragma unroll
            for (int r = 0; r < R; r++) {
                const float4 xv = *(const float4*)(Xs + (r0 + r) * xstride + k);
                acc0[r] = fmaf(xv.x, w0[0], acc0[r]);
                acc0[r] = fmaf(xv.y, w0[1], acc0[r]);
                acc0[r] = fmaf(xv.z, w0[2], acc0[r]);
                acc0[r] = fmaf(xv.w, w0[3], acc0[r]);
                if (FO == 64) {
                    acc1[r] = fmaf(xv.x, w1[0], acc1[r]);
                    acc1[r] = fmaf(xv.y, w1[1], acc1[r]);
                    acc1[r] = fmaf(xv.z, w1[2], acc1[r]);
                    acc1[r] = fmaf(xv.w, w1[3], acc1[r]);
                }
            }
        }
        #pragma unroll
        for (int r = 0; r < R; r++) {
            int n = row0 + r0 + r;
            float inv = invsh[n];
            if (FO >= 32 || lane < FO) Ys[n * FO + c0] = acc0[r] * inv;
            if (FO == 64)              Ys[n * FO + c0 + 32] = acc1[r] * inv;
        }
    }
}

// ---------------- aggregation, direct write (layers 1,2) ----------------
template<int FO>
__device__ __forceinline__ void agg_direct(
    const float* __restrict__ Ys, float* __restrict__ Out,
    const ushort4* __restrict__ csr4, const unsigned short* __restrict__ offsh,
    const float* __restrict__ invsh, const unsigned char* __restrict__ padsh,
    const float* __restrict__ bias, bool relu, int warp, int lane)
{
    const int c0 = lane & (FO - 1);
    const float b0 = __ldg(bias + c0);
    for (int n = warp; n < NPG; n += 16) {
        int q0 = offsh[n] >> 2, q1 = offsh[n + 1] >> 2;
        float a0 = 0.f;
        for (int q = q0; q < q1; q++) {
            ushort4 ix = csr4[q];
            a0 += Ys[ix.x * FO + c0];
            a0 += Ys[ix.y * FO + c0];
            a0 += Ys[ix.z * FO + c0];
            a0 += Ys[ix.w * FO + c0];
        }
        float corr = 1.f - (float)padsh[n];
        a0 = fmaf(corr, Ys[n * FO + c0], a0);
        float o0 = a0 * invsh[n] + b0;
        if (relu) o0 = fmaxf(o0, 0.f);
        if (FO >= 32 || lane < FO) Out[n * FO + c0] = o0;
    }
}

// ---------------- resize-tap projection ----------------
template<int FO>
__device__ __forceinline__ void taps(const float* __restrict__ Hs, int stride,
                                     float* __restrict__ uout, int tid)
{
    for (int t = tid; t < 10 * FO; t += 512) {
        int p = t / FO, d = t % FO;
        float c = (p + 0.5f) * 51.2f - 0.5f;
        int i0 = (int)floorf(c);
        float w = c - (float)i0;
        uout[p * 64 + d] = Hs[i0 * stride + d] * (1.f - w) + Hs[(i0 + 1) * stride + d] * w;
    }
}

// ---------------- fused per-(graph,side) kernel ----------------
__global__ void __launch_bounds__(512, 1)
k_fused(const float* __restrict__ x0, const float* __restrict__ x1,
        const float* __restrict__ W0, const float* __restrict__ b0,
        const float* __restrict__ W1, const float* __restrict__ b1,
        const float* __restrict__ W2, const float* __restrict__ b2,
        const int* __restrict__ ei, const int* __restrict__ ej)
{
    extern __shared__ char smraw[];
    float*          xbuf  = (float*)(smraw + OFF_XBUF);
    float*          ybuf  = (float*)(smraw + OFF_YBUF);
    unsigned short* csr   = (unsigned short*)(smraw + OFF_CSR);
    const ushort4*  csr4  = (const ushort4*)csr;
    unsigned short* offsh = (unsigned short*)(smraw + OFF_OFFS);
    float*          invsh = (float*)(smraw + OFF_INV);
    unsigned char*  padsh = (unsigned char*)(smraw + OFF_PAD);

    const int side = blockIdx.y, g = blockIdx.x;
    const int tid = threadIdx.x, warp = tid >> 5, lane = tid & 31;
    const int* E    = side ? ej : ei;
    const int* esrc = E + g * EPG;
    const int* edst = E + NEDGE + g * EPG;
    const float* xin = side ? x1 : x0;

    // ---- build padded CSR in SMEM (scratch ints live in ybuf) ----
    int* cnt  = (int*)ybuf;          // [512]
    int* cur  = cnt + 512;           // [512]
    int* wtot = cnt + 1024;          // [16]
    cnt[tid] = 0;
    __syncthreads();
    for (int e = tid; e < EPG; e += 512) atomicAdd(&cnt[edst[e] & (NPG - 1)], 1);
    __syncthreads();
    int deg = cnt[tid];
    int pc  = (deg + 3) & ~3;
    // warp-shuffle inclusive scan of pc
    int s = pc;
    #pragma unroll
    for (int d = 1; d < 32; d <<= 1) {
        int v = __shfl_up_sync(0xffffffffu, s, d);
        if (lane >= d) s += v;
    }
    if (lane == 31) wtot[warp] = s;
    __syncthreads();
    if (tid < 16) {
        int t = wtot[tid];
        #pragma unroll
        for (int d = 1; d < 16; d <<= 1) {
            int v = __shfl_up_sync(0x0000ffffu, t, d);
            if (tid >= d) t += v;
        }
        wtot[tid] = t;
    }
    __syncthreads();
    int base = warp ? wtot[warp - 1] : 0;
    int off  = base + s - pc;                 // exclusive padded offset
    offsh[tid] = (unsigned short)off;
    if (tid == 511) offsh[512] = (unsigned short)(off + pc);
    invsh[tid] = rsqrtf((float)deg + 1.0f);
    padsh[tid] = (unsigned char)(pc - deg);
    cur[tid] = off;
    __syncthreads();
    for (int e = tid; e < EPG; e += 512) {
        int sv = esrc[e] & (NPG - 1), dv = edst[e] & (NPG - 1);
        int p = atomicAdd(&cur[dv], 1);
        csr[p] = (unsigned short)sv;
    }
    for (int t = deg; t < pc; t++) csr[off + t] = (unsigned short)tid;  // self pads
    __syncthreads();

    // ---- layer 0: XW in two 256-row chunks staged through ybuf ----
    for (int ch = 0; ch < 2; ch++) {
        const float4* src = (const float4*)(xin + ((size_t)g * NPG + ch * 256) * 64);
        float4* dst = (float4*)ybuf;
        for (int i = tid; i < 4096; i += 512) dst[i] = src[i];
        __syncthreads();
        xw_stage<64, 64, 8>(ybuf, 64, ch * 256, 256, xbuf, W0, invsh, warp, lane);
        __syncthreads();
    }

    // ---- agg0 (gather from xbuf, stage h0 in registers, write back) ----
    {
        float h0[32], h1[32];
        const float bb0 = __ldg(b0 + lane);
        const float bb1 = __ldg(b0 + lane + 32);
        #pragma unroll
        for (int it = 0; it < 32; it++) {
            int n = warp + it * 16;
            int q0 = offsh[n] >> 2, q1 = offsh[n + 1] >> 2;
            float a0 = 0.f, a1 = 0.f;
            for (int q = q0; q < q1; q++) {
                ushort4 ix = csr4[q];
                a0 += xbuf[ix.x * 64 + lane];  a1 += xbuf[ix.x * 64 + lane + 32];
                a0 += xbuf[ix.y * 64 + lane];  a1 += xbuf[ix.y * 64 + lane + 32];
                a0 += xbuf[ix.z * 64 + lane];  a1 += xbuf[ix.z * 64 + lane + 32];
                a0 += xbuf[ix.w * 64 + lane];  a1 += xbuf[ix.w * 64 + lane + 32];
            }
            float corr = 1.f - (float)padsh[n];
            a0 = fmaf(corr, xbuf[n * 64 + lane], a0);
            a1 = fmaf(corr, xbuf[n * 64 + lane + 32], a1);
            float inv = invsh[n];
            h0[it] = fmaxf(a0 * inv + bb0, 0.f);
            h1[it] = fmaxf(a1 * inv + bb1, 0.f);
        }
        __syncthreads();
        #pragma unroll
        for (int it = 0; it < 32; it++) {
            int n = warp + it * 16;
            xbuf[n * 64 + lane] = h0[it];
            xbuf[n * 64 + lane + 32] = h1[it];
        }
        __syncthreads();
    }

    // ---- taps0 + XW1 (both read xbuf only) ----
    taps<64>(xbuf, 64, &g_u[side][0][g * 640], tid);
    xw_stage<64, 32, 8>(xbuf, 64, 0, NPG, ybuf, W1, invsh, warp, lane);
    __syncthreads();

    // ---- agg1: ybuf -> xbuf (stride 32) ----
    agg_direct<32>(ybuf, xbuf, csr4, offsh, invsh, padsh, b1, true, warp, lane);
    __syncthreads();

    // ---- taps1 + XW2: xbuf(stride32) -> ybuf(512x16) ----
    taps<32>(xbuf, 32, &g_u[side][1][g * 640], tid);
    xw_stage<32, 16, 8>(xbuf, 32, 0, NPG, ybuf, W2, invsh, warp, lane);
    __syncthreads();

    // ---- agg2: ybuf -> xbuf (stride 16), no relu ----
    agg_direct<16>(ybuf, xbuf, csr4, offsh, invsh, padsh, b2, false, warp, lane);
    __syncthreads();

    // ---- taps2 ----
    taps<16>(xbuf, 16, &g_u[side][2][g * 640], tid);
}

// ---------------- head: 10x10 sims + conv3x3 + MLP + sigmoid ----------------
__global__ void __launch_bounds__(512)
k_head(const float* __restrict__ cw0, const float* __restrict__ cb0,
       const float* __restrict__ cw1, const float* __restrict__ cb1,
       const float* __restrict__ cw2, const float* __restrict__ cb2,
       const float* __restrict__ mw0, const float* __restrict__ mb0,
       const float* __restrict__ mw1, const float* __restrict__ mb1,
       const float* __restrict__ mw2, const float* __restrict__ mb2,
       const float* __restrict__ mw3, const float* __restrict__ mb3,
       const float* __restrict__ mw4, const float* __restrict__ mb4,
       const float* __restrict__ sw,  const float* __restrict__ sb,
       float* __restrict__ out) {
    int b = blockIdx.x, tid = threadIdx.x, warp = tid >> 5, lane = tid & 31;
    __shared__ float ui[3][640], uj[3][640];
    __shared__ float sim[100];
    __shared__ float feat[2400];
    __shared__ float red[16][32];

    for (int t = tid; t < 1920; t += 512) {
        int l = t / 640, r = t % 640;
        ui[l][r] = g_u[0][l][b*640 + r];
        uj[l][r] = g_u[1][l][b*640 + r];
    }
    __syncthreads();

    const int FOs[3] = {64, 32, 16};
    for (int l = 0; l < 3; l++) {
        int fo = FOs[l];
        // sim: warp per entry, lane-parallel over d + shuffle reduce
        for (int ent = warp; ent < 100; ent += 16) {
            int p = ent / 10, q = ent % 10;
            float s = 0.f;
            for (int d = lane; d < fo; d += 32)
                s = fmaf(ui[l][p*64 + d], uj[l][q*64 + d], s);
            #pragma unroll
            for (int o = 16; o; o >>= 1) s += __shfl_xor_sync(0xffffffffu, s, o);
            if (lane == 0) sim[ent] = s;
        }
        __syncthreads();
        const float* cw = (l==0) ? cw0 : (l==1) ? cw1 : cw2;
        const float* cb = (l==0) ? cb0 : (l==1) ? cb1 : cb2;
        for (int t = tid; t < 800; t += 512) {
            int ch = t/100, rc = t%100, r = rc/10, c = rc%10;
            float acc = __ldg(cb + ch);
            #pragma unroll
            for (int dr = 0; dr < 3; dr++)
                #pragma unroll
                for (int dc = 0; dc < 3; dc++) {
                    int rr = r + dr - 1, cc = c + dc - 1;
                    if (rr >= 0 && rr < 10 && cc >= 0 && cc < 10)
                        acc = fmaf(__ldg(cw + ch*9 + dr*3 + dc), sim[rr*10+cc], acc);
                }
            feat[l*800 + t] = fmaxf(acc, 0.f);
        }
        __syncthreads();
    }

    // MLP0: 2400 -> 32, 16-way split-K across warps
    {
        float acc = 0.f;
        for (int k = warp; k < 2400; k += 16)
            acc = fmaf(feat[k], __ldg(mw0 + k*32 + lane), acc);
        red[warp][lane] = acc;
    }
    __syncthreads();

    if (warp == 0) {
        float s = __ldg(mb0 + lane);
        #pragma unroll
        for (int p = 0; p < 16; p++) s += red[p][lane];
        float a0 = fmaxf(s, 0.f);

        float a1 = (lane < 16) ? __ldg(mb1 + lane) : 0.f;
        #pragma unroll
        for (int k = 0; k < 32; k++) {
            float v = __shfl_sync(0xffffffffu, a0, k);
            if (lane < 16) a1 = fmaf(v, __ldg(mw1 + k*16 + lane), a1);
        }
        a1 = fmaxf(a1, 0.f);

        float a2 = (lane < 8) ? __ldg(mb2 + lane) : 0.f;
        #pragma unroll
        for (int k = 0; k < 16; k++) {
            float v = __shfl_sync(0xffffffffu, a1, k);
            if (lane < 8) a2 = fmaf(v, __ldg(mw2 + k*8 + lane), a2);
        }
        a2 = fmaxf(a2, 0.f);

        float a3 = (lane < 4) ? __ldg(mb3 + lane) : 0.f;
        #pragma unroll
        for (int k = 0; k < 8; k++) {
            float v = __shfl_sync(0xffffffffu, a2, k);
            if (lane < 4) a3 = fmaf(v, __ldg(mw3 + k*4 + lane), a3);
        }
        a3 = fmaxf(a3, 0.f);

        float v0 = __shfl_sync(0xffffffffu, a3, 0);
        float v1 = __shfl_sync(0xffffffffu, a3, 1);
        float v2 = __shfl_sync(0xffffffffu, a3, 2);
        float v3 = __shfl_sync(0xffffffffu, a3, 3);
        if (lane == 0) {
            float s4 = __ldg(mb4);
            s4 = fmaf(v0, __ldg(mw4 + 0), s4);
            s4 = fmaf(v1, __ldg(mw4 + 1), s4);
            s4 = fmaf(v2, __ldg(mw4 + 2), s4);
            s4 = fmaf(v3, __ldg(mw4 + 3), s4);
            float f = fmaxf(s4, 0.f);
            float sc = f * __ldg(sw) + __ldg(sb);
            out[b] = 1.f / (1.f + expf(-sc));
        }
    }
}

// ---------------- launch ----------------
extern "C" void kernel_launch(void* const* d_in, const int* in_sizes, int n_in,
                              void* d_out, int out_size) {
    const float* x_i = (const float*)d_in[0];
    const float* x_j = (const float*)d_in[1];
    const float* gw0 = (const float*)d_in[2];  const float* gb0 = (const float*)d_in[3];
    const float* gw1 = (const float*)d_in[4];  const float* gb1 = (const float*)d_in[5];
    const float* gw2 = (const float*)d_in[6];  const float* gb2 = (const float*)d_in[7];
    const float* cw0 = (const float*)d_in[8];  const float* cb0 = (const float*)d_in[9];
    const float* cw1 = (const float*)d_in[10]; const float* cb1 = (const float*)d_in[11];
    const float* cw2 = (const float*)d_in[12]; const float* cb2 = (const float*)d_in[13];
    const float* mw0 = (const float*)d_in[14]; const float* mb0 = (const float*)d_in[15];
    const float* mw1 = (const float*)d_in[16]; const float* mb1 = (const float*)d_in[17];
    const float* mw2 = (const float*)d_in[18]; const float* mb2 = (const float*)d_in[19];
    const float* mw3 = (const float*)d_in[20]; const float* mb3 = (const float*)d_in[21];
    const float* mw4 = (const float*)d_in[22]; const float* mb4 = (const float*)d_in[23];
    const float* sw  = (const float*)d_in[24]; const float* sb  = (const float*)d_in[25];
    const int*   ei  = (const int*)d_in[26];
    const int*   ej  = (const int*)d_in[27];

    cudaFuncSetAttribute(k_fused, cudaFuncAttributeMaxDynamicSharedMemorySize, SMEM_BYTES);

    k_fused<<<dim3(BGRAPH, 2), 512, SMEM_BYTES>>>(x_i, x_j, gw0, gb0, gw1, gb1, gw2, gb2, ei, ej);
    k_head<<<BGRAPH, 512>>>(cw0, cb0, cw1, cb1, cw2, cb2,
                            mw0, mb0, mw1, mb1, mw2, mb2, mw3, mb3, mw4, mb4,
                            sw, sb, (float*)d_out);
}

// round 5
// speedup vs baseline: 3.2162x; 1.3305x over previous
#include <cuda_runtime.h>
#include <math.h>

#define BGRAPH 128
#define NPG    512
#define NNODES (BGRAPH*NPG)
#define EPG    (NPG*16)
#define NEDGE  (NNODES*16)
#define NT     1024
#define NW     32

// cross-kernel scratch: resize-tap projections
__device__ float g_u[2][3][BGRAPH*640];

// SMEM byte offsets for k_fused
#define OFF_XBUF 0          // 512*64 f = 131072
#define OFF_YBUF 131072     // 512*32 f =  65536
#define OFF_CSR  196608     // ushort[9728] = 19456
#define OFF_OFFS 216064     // ushort[513] -> 1032 (padded)
#define OFF_INV  217096     // float[512] = 2048
#define OFF_PAD  219144     // uchar[512] = 512
#define OFF_SCR  219656     // int[1040] = 4160 (cnt/cur/wtot, later tmp)
#define SMEM_BYTES 223816

// ---------------- XW stage: Y[n,c] = (sum_k X[n,k] W[k,c]) * inv[n] ----------------
template<int FI, int FO, int R>
__device__ __forceinline__ void xw_stage(
    const float* __restrict__ Xs, int xstride, int row0, int nrows,
    float* __restrict__ Ys, const float* __restrict__ W,
    const float* __restrict__ invsh, int warp, int lane)
{
    const int c0 = lane & (FO - 1);
    for (int grp = warp; grp < nrows / R; grp += NW) {
        int r0 = grp * R;
        float acc0[R], acc1[R];
        #pragma unroll
        for (int r = 0; r < R; r++) { acc0[r] = 0.f; acc1[r] = 0.f; }
        #pragma unroll 4
        for (int k = 0; k < FI; k += 4) {
            float w0[4], w1[4];
            #pragma unroll
            for (int q = 0; q < 4; q++) {
                w0[q] = __ldg(W + (k + q) * FO + c0);
                if (FO == 64) w1[q] = __ldg(W + (k + q) * FO + c0 + 32);
            }
            #pragma unroll
            for (int r = 0; r < R; r++) {
                const float4 xv = *(const float4*)(Xs + (r0 + r) * xstride + k);
                acc0[r] = fmaf(xv.x, w0[0], acc0[r]);
                acc0[r] = fmaf(xv.y, w0[1], acc0[r]);
                acc0[r] = fmaf(xv.z, w0[2], acc0[r]);
                acc0[r] = fmaf(xv.w, w0[3], acc0[r]);
                if (FO == 64) {
                    acc1[r] = fmaf(xv.x, w1[0], acc1[r]);
                    acc1[r] = fmaf(xv.y, w1[1], acc1[r]);
                    acc1[r] = fmaf(xv.z, w1[2], acc1[r]);
                    acc1[r] = fmaf(xv.w, w1[3], acc1[r]);
                }
            }
        }
        #pragma unroll
        for (int r = 0; r < R; r++) {
            int n = row0 + r0 + r;
            float inv = invsh[n];
            if (FO >= 32 || lane < FO) Ys[n * FO + c0] = acc0[r] * inv;
            if (FO == 64)              Ys[n * FO + c0 + 32] = acc1[r] * inv;
        }
    }
}

// ---------------- aggregation, direct write (layer 1) ----------------
template<int FO>
__device__ __forceinline__ void agg_direct(
    const float* __restrict__ Ys, float* __restrict__ Out,
    const ushort4* __restrict__ csr4, const unsigned short* __restrict__ offsh,
    const float* __restrict__ invsh, const unsigned char* __restrict__ padsh,
    const float* __restrict__ bias, bool relu, int warp, int lane)
{
    const int c0 = lane & (FO - 1);
    const float b0 = __ldg(bias + c0);
    for (int n = warp; n < NPG; n += NW) {
        int q0 = offsh[n] >> 2, q1 = offsh[n + 1] >> 2;
        float a0 = 0.f;
        for (int q = q0; q < q1; q++) {
            ushort4 ix = csr4[q];
            a0 += Ys[ix.x * FO + c0];
            a0 += Ys[ix.y * FO + c0];
            a0 += Ys[ix.z * FO + c0];
            a0 += Ys[ix.w * FO + c0];
        }
        float corr = 1.f - (float)padsh[n];
        a0 = fmaf(corr, Ys[n * FO + c0], a0);
        float o0 = a0 * invsh[n] + b0;
        if (relu) o0 = fmaxf(o0, 0.f);
        if (FO >= 32 || lane < FO) Out[n * FO + c0] = o0;
    }
}

// ---------------- resize-tap projection ----------------
template<int FO>
__device__ __forceinline__ void taps(const float* __restrict__ Hs, int stride,
                                     float* __restrict__ uout, int tid)
{
    for (int t = tid; t < 10 * FO; t += NT) {
        int p = t / FO, d = t % FO;
        float c = (p + 0.5f) * 51.2f - 0.5f;
        int i0 = (int)floorf(c);
        float w = c - (float)i0;
        uout[p * 64 + d] = Hs[i0 * stride + d] * (1.f - w) + Hs[(i0 + 1) * stride + d] * w;
    }
}

// ---------------- fused per-(graph,side) kernel ----------------
__global__ void __launch_bounds__(NT, 1)
k_fused(const float* __restrict__ x0, const float* __restrict__ x1,
        const float* __restrict__ W0, const float* __restrict__ b0,
        const float* __restrict__ W1, const float* __restrict__ b1,
        const float* __restrict__ W2, const float* __restrict__ b2,
        const int* __restrict__ ei, const int* __restrict__ ej)
{
    extern __shared__ char smraw[];
    float*          xbuf  = (float*)(smraw + OFF_XBUF);
    float*          ybuf  = (float*)(smraw + OFF_YBUF);
    unsigned short* csr   = (unsigned short*)(smraw + OFF_CSR);
    const ushort4*  csr4  = (const ushort4*)csr;
    unsigned short* offsh = (unsigned short*)(smraw + OFF_OFFS);
    float*          invsh = (float*)(smraw + OFF_INV);
    unsigned char*  padsh = (unsigned char*)(smraw + OFF_PAD);
    int*            cnt   = (int*)(smraw + OFF_SCR);   // [512]
    int*            cur   = cnt + 512;                 // [512]
    int*            wtot  = cnt + 1024;                // [16]

    const int side = blockIdx.y, g = blockIdx.x;
    const int tid = threadIdx.x, warp = tid >> 5, lane = tid & 31;
    const int* E    = side ? ej : ei;
    const int* esrc = E + g * EPG;
    const int* edst = E + NEDGE + g * EPG;
    const float* xin = side ? x1 : x0;

    // ---- phase A: zero counts + preload X chunk0 into ybuf ----
    if (tid < 512) cnt[tid] = 0;
    {
        const float4* src = (const float4*)(xin + (size_t)g * NPG * 64);
        float4* dst = (float4*)ybuf;
        for (int i = tid; i < 4096; i += NT) dst[i] = src[i];
    }
    __syncthreads();
    for (int e = tid; e < EPG; e += NT) atomicAdd(&cnt[edst[e] & (NPG - 1)], 1);
    __syncthreads();

    // ---- scan (warps 0-15 only) ----
    int deg = 0, pc = 0, s_incl = 0, off = 0;
    if (tid < 512) {
        deg = cnt[tid];
        pc  = (deg + 3) & ~3;
        s_incl = pc;
        #pragma unroll
        for (int d = 1; d < 32; d <<= 1) {
            int v = __shfl_up_sync(0xffffffffu, s_incl, d);
            if (lane >= d) s_incl += v;
        }
        if (lane == 31) wtot[warp] = s_incl;
    }
    __syncthreads();
    if (tid < 16) {
        int t = wtot[tid];
        #pragma unroll
        for (int d = 1; d < 16; d <<= 1) {
            int v = __shfl_up_sync(0x0000ffffu, t, d);
            if (tid >= d) t += v;
        }
        wtot[tid] = t;
    }
    __syncthreads();
    if (tid < 512) {
        int base = warp ? wtot[warp - 1] : 0;
        off = base + s_incl - pc;
        offsh[tid] = (unsigned short)off;
        if (tid == 511) offsh[512] = (unsigned short)(off + pc);
        invsh[tid] = rsqrtf((float)deg + 1.0f);
        padsh[tid] = (unsigned char)(pc - deg);
        cur[tid] = off;
    }
    __syncthreads();
    for (int e = tid; e < EPG; e += NT) {
        int sv = esrc[e] & (NPG - 1), dv = edst[e] & (NPG - 1);
        int p = atomicAdd(&cur[dv], 1);
        csr[p] = (unsigned short)sv;
    }
    if (tid < 512)
        for (int t = deg; t < pc; t++) csr[off + t] = (unsigned short)tid;
    __syncthreads();

    // ---- layer 0 XW, chunk 0 (ybuf already holds rows 0-255) ----
    xw_stage<64, 64, 8>(ybuf, 64, 0, 256, xbuf, W0, invsh, warp, lane);
    __syncthreads();
    {
        const float4* src = (const float4*)(xin + ((size_t)g * NPG + 256) * 64);
        float4* dst = (float4*)ybuf;
        for (int i = tid; i < 4096; i += NT) dst[i] = src[i];
    }
    __syncthreads();
    xw_stage<64, 64, 8>(ybuf, 64, 256, 256, xbuf, W0, invsh, warp, lane);
    __syncthreads();

    // ---- agg0: gather xbuf, stage in regs, write back ----
    {
        float h0[16], h1[16];
        const float bb0 = __ldg(b0 + lane);
        const float bb1 = __ldg(b0 + lane + 32);
        #pragma unroll
        for (int it = 0; it < 16; it++) {
            int n = warp + it * NW;
            int q0 = offsh[n] >> 2, q1 = offsh[n + 1] >> 2;
            float a0 = 0.f, a1 = 0.f;
            for (int q = q0; q < q1; q++) {
                ushort4 ix = csr4[q];
                a0 += xbuf[ix.x * 64 + lane];  a1 += xbuf[ix.x * 64 + lane + 32];
                a0 += xbuf[ix.y * 64 + lane];  a1 += xbuf[ix.y * 64 + lane + 32];
                a0 += xbuf[ix.z * 64 + lane];  a1 += xbuf[ix.z * 64 + lane + 32];
                a0 += xbuf[ix.w * 64 + lane];  a1 += xbuf[ix.w * 64 + lane + 32];
            }
            float corr = 1.f - (float)padsh[n];
            a0 = fmaf(corr, xbuf[n * 64 + lane], a0);
            a1 = fmaf(corr, xbuf[n * 64 + lane + 32], a1);
            float inv = invsh[n];
            h0[it] = fmaxf(a0 * inv + bb0, 0.f);
            h1[it] = fmaxf(a1 * inv + bb1, 0.f);
        }
        __syncthreads();
        #pragma unroll
        for (int it = 0; it < 16; it++) {
            int n = warp + it * NW;
            xbuf[n * 64 + lane] = h0[it];
            xbuf[n * 64 + lane + 32] = h1[it];
        }
        __syncthreads();
    }

    // ---- taps0 + XW1 ----
    taps<64>(xbuf, 64, &g_u[side][0][g * 640], tid);
    xw_stage<64, 32, 8>(xbuf, 64, 0, NPG, ybuf, W1, invsh, warp, lane);
    __syncthreads();

    // ---- agg1: ybuf -> xbuf ----
    agg_direct<32>(ybuf, xbuf, csr4, offsh, invsh, padsh, b1, true, warp, lane);
    __syncthreads();

    // ---- taps1 + XW2 ----
    taps<32>(xbuf, 32, &g_u[side][1][g * 640], tid);
    xw_stage<32, 16, 8>(xbuf, 32, 0, NPG, ybuf, W2, invsh, warp, lane);
    __syncthreads();

    // ---- fused agg2 + taps2: only the 20 tap rows ----
    float* tmp = (float*)cnt;   // [20*16], cnt scratch is dead now
    if (warp < 20) {
        int p = warp >> 1;
        float c = (p + 0.5f) * 51.2f - 0.5f;
        int i0 = (int)floorf(c);
        int r = i0 + (warp & 1);
        int c0 = lane & 15;
        int q0 = offsh[r] >> 2, q1 = offsh[r + 1] >> 2;
        float a = 0.f;
        for (int q = q0; q < q1; q++) {
            ushort4 ix = csr4[q];
            a += ybuf[ix.x * 16 + c0];
            a += ybuf[ix.y * 16 + c0];
            a += ybuf[ix.z * 16 + c0];
            a += ybuf[ix.w * 16 + c0];
        }
        a = fmaf(1.f - (float)padsh[r], ybuf[r * 16 + c0], a);
        tmp[warp * 16 + c0] = a * invsh[r] + __ldg(b2 + c0);
    }
    __syncthreads();
    if (tid < 160) {
        int p = tid >> 4, d = tid & 15;
        float c = (p + 0.5f) * 51.2f - 0.5f;
        int i0 = (int)floorf(c);
        float w = c - (float)i0;
        g_u[side][2][g * 640 + p * 64 + d] =
            tmp[(2 * p) * 16 + d] * (1.f - w) + tmp[(2 * p + 1) * 16 + d] * w;
    }
}

// ---------------- head: sims + conv3x3 + MLP + sigmoid ----------------
__global__ void __launch_bounds__(512)
k_head(const float* __restrict__ cw0, const float* __restrict__ cb0,
       const float* __restrict__ cw1, const float* __restrict__ cb1,
       const float* __restrict__ cw2, const float* __restrict__ cb2,
       const float* __restrict__ mw0, const float* __restrict__ mb0,
       const float* __restrict__ mw1, const float* __restrict__ mb1,
       const float* __restrict__ mw2, const float* __restrict__ mb2,
       const float* __restrict__ mw3, const float* __restrict__ mb3,
       const float* __restrict__ mw4, const float* __restrict__ mb4,
       const float* __restrict__ sw,  const float* __restrict__ sb,
       float* __restrict__ out) {
    int b = blockIdx.x, tid = threadIdx.x, warp = tid >> 5, lane = tid & 31;
    __shared__ float ui[3][640], uj[3][640];
    __shared__ float sim[3][100];
    __shared__ float feat[2400];
    __shared__ float red[16][32];
    __shared__ float cwsm[3][72], cbsm[3][8];
    __shared__ float w1s[512], w2s[128], w3s[32], w4s[4];
    __shared__ float b0s[32], b1s[16], b2s[8], b3s[4], sconst[3];

    for (int t = tid; t < 1920; t += 512) {
        int l = t / 640, r = t % 640;
        ui[l][r] = g_u[0][l][b*640 + r];
        uj[l][r] = g_u[1][l][b*640 + r];
    }
    for (int t = tid; t < 512; t += 512) w1s[t] = __ldg(mw1 + t);
    if (tid < 72) { cwsm[0][tid] = __ldg(cw0+tid); cwsm[1][tid] = __ldg(cw1+tid); cwsm[2][tid] = __ldg(cw2+tid); }
    if (tid >= 96 && tid < 104) { int c = tid-96; cbsm[0][c] = __ldg(cb0+c); cbsm[1][c] = __ldg(cb1+c); cbsm[2][c] = __ldg(cb2+c); }
    if (tid >= 128 && tid < 256) w2s[tid-128] = __ldg(mw2 + tid-128);
    if (tid >= 256 && tid < 288) w3s[tid-256] = __ldg(mw3 + tid-256);
    if (tid >= 288 && tid < 292) w4s[tid-288] = __ldg(mw4 + tid-288);
    if (tid >= 320 && tid < 352) b0s[tid-320] = __ldg(mb0 + tid-320);
    if (tid >= 352 && tid < 368) b1s[tid-352] = __ldg(mb1 + tid-352);
    if (tid >= 384 && tid < 392) b2s[tid-384] = __ldg(mb2 + tid-384);
    if (tid >= 416 && tid < 420) b3s[tid-416] = __ldg(mb3 + tid-416);
    if (tid == 448) sconst[0] = __ldg(mb4);
    if (tid == 449) sconst[1] = __ldg(sw);
    if (tid == 450) sconst[2] = __ldg(sb);
    __syncthreads();

    // all 3 layers' sims concurrently: 300 warp-tasks
    for (int ent = warp; ent < 300; ent += 16) {
        int l = ent / 100, e = ent % 100;
        int p = e / 10, q = e % 10;
        int fo = 64 >> l;
        float s = 0.f;
        for (int d = lane; d < fo; d += 32)
            s = fmaf(ui[l][p*64 + d], uj[l][q*64 + d], s);
        #pragma unroll
        for (int o = 16; o; o >>= 1) s += __shfl_xor_sync(0xffffffffu, s, o);
        if (lane == 0) sim[l][e] = s;
    }
    __syncthreads();

    // conv3x3 + relu -> feat (all from SMEM)
    for (int t = tid; t < 2400; t += 512) {
        int l = t / 800, u = t % 800;
        int ch = u / 100, rc = u % 100, r = rc / 10, c = rc % 10;
        float acc = cbsm[l][ch];
        #pragma unroll
        for (int dr = 0; dr < 3; dr++)
            #pragma unroll
            for (int dc = 0; dc < 3; dc++) {
                int rr = r + dr - 1, cc = c + dc - 1;
                if (rr >= 0 && rr < 10 && cc >= 0 && cc < 10)
                    acc = fmaf(cwsm[l][ch*9 + dr*3 + dc], sim[l][rr*10 + cc], acc);
            }
        feat[t] = fmaxf(acc, 0.f);
    }
    __syncthreads();

    // MLP0: 2400 -> 32, 16-way split-K (mw0 stays global: 307KB)
    {
        float acc = 0.f;
        #pragma unroll 5
        for (int k = warp; k < 2400; k += 16)
            acc = fmaf(feat[k], __ldg(mw0 + k*32 + lane), acc);
        red[warp][lane] = acc;
    }
    __syncthreads();

    if (warp == 0) {
        float s = b0s[lane];
        #pragma unroll
        for (int p = 0; p < 16; p++) s += red[p][lane];
        float a0 = fmaxf(s, 0.f);

        float a1 = (lane < 16) ? b1s[lane] : 0.f;
        #pragma unroll
        for (int k = 0; k < 32; k++) {
            float v = __shfl_sync(0xffffffffu, a0, k);
            if (lane < 16) a1 = fmaf(v, w1s[k*16 + lane], a1);
        }
        a1 = fmaxf(a1, 0.f);

        float a2 = (lane < 8) ? b2s[lane] : 0.f;
        #pragma unroll
        for (int k = 0; k < 16; k++) {
            float v = __shfl_sync(0xffffffffu, a1, k);
            if (lane < 8) a2 = fmaf(v, w2s[k*8 + lane], a2);
        }
        a2 = fmaxf(a2, 0.f);

        float a3 = (lane < 4) ? b3s[lane] : 0.f;
        #pragma unroll
        for (int k = 0; k < 8; k++) {
            float v = __shfl_sync(0xffffffffu, a2, k);
            if (lane < 4) a3 = fmaf(v, w3s[k*4 + lane], a3);
        }
        a3 = fmaxf(a3, 0.f);

        float v0 = __shfl_sync(0xffffffffu, a3, 0);
        float v1 = __shfl_sync(0xffffffffu, a3, 1);
        float v2 = __shfl_sync(0xffffffffu, a3, 2);
        float v3 = __shfl_sync(0xffffffffu, a3, 3);
        if (lane == 0) {
            float s4 = sconst[0];
            s4 = fmaf(v0, w4s[0], s4);
            s4 = fmaf(v1, w4s[1], s4);
            s4 = fmaf(v2, w4s[2], s4);
            s4 = fmaf(v3, w4s[3], s4);
            float f = fmaxf(s4, 0.f);
            float sc = f * sconst[1] + sconst[2];
            out[b] = 1.f / (1.f + expf(-sc));
        }
    }
}

// ---------------- launch ----------------
extern "C" void kernel_launch(void* const* d_in, const int* in_sizes, int n_in,
                              void* d_out, int out_size) {
    const float* x_i = (const float*)d_in[0];
    const float* x_j = (const float*)d_in[1];
    const float* gw0 = (const float*)d_in[2];  const float* gb0 = (const float*)d_in[3];
    const float* gw1 = (const float*)d_in[4];  const float* gb1 = (const float*)d_in[5];
    const float* gw2 = (const float*)d_in[6];  const float* gb2 = (const float*)d_in[7];
    const float* cw0 = (const float*)d_in[8];  const float* cb0 = (const float*)d_in[9];
    const float* cw1 = (const float*)d_in[10]; const float* cb1 = (const float*)d_in[11];
    const float* cw2 = (const float*)d_in[12]; const float* cb2 = (const float*)d_in[13];
    const float* mw0 = (const float*)d_in[14]; const float* mb0 = (const float*)d_in[15];
    const float* mw1 = (const float*)d_in[16]; const float* mb1 = (const float*)d_in[17];
    const float* mw2 = (const float*)d_in[18]; const float* mb2 = (const float*)d_in[19];
    const float* mw3 = (const float*)d_in[20]; const float* mb3 = (const float*)d_in[21];
    const float* mw4 = (const float*)d_in[22]; const float* mb4 = (const float*)d_in[23];
    const float* sw  = (const float*)d_in[24]; const float* sb  = (const float*)d_in[25];
    const int*   ei  = (const int*)d_in[26];
    const int*   ej  = (const int*)d_in[27];

    cudaFuncSetAttribute(k_fused, cudaFuncAttributeMaxDynamicSharedMemorySize, SMEM_BYTES);

    k_fused<<<dim3(BGRAPH, 2), NT, SMEM_BYTES>>>(x_i, x_j, gw0, gb0, gw1, gb1, gw2, gb2, ei, ej);
    k_head<<<BGRAPH, 512>>>(cw0, cb0, cw1, cb1, cw2, cb2,
                            mw0, mb0, mw1, mb1, mw2, mb2, mw3, mb3, mw4, mb4,
                            sw, sb, (float*)d_out);
}